// round 10
// baseline (speedup 1.0000x reference)
#include <cuda_runtime.h>
#include <cuda_bf16.h>
#include <cstdint>

// Problem constants (fixed by the dataset)
constexpr int N_SRC   = 100000;
constexpr int N_TGT   = 50000;
constexpr int N_EDGES = 600000;
constexpr int C       = 128;   // in/out channels
constexpr int R       = 7;     // edge types
constexpr int T       = 4;     // node types
constexpr int KREL    = R * C;        // 896
constexpr int KTOT    = KREL + T * C; // 1408

// Scratch (static __device__ arrays: allocation-free per harness rules)
__device__ int g_dcnt[N_TGT];          // per-dst edge count (histogram)
__device__ int g_doff[N_TGT + 1];      // CSR offsets
__device__ int g_cur[N_TGT];           // fill cursors
__device__ int g_elist[N_EDGES];       // CSR edge ids
__device__ __nv_bfloat16 g_Ahi[(size_t)N_TGT * KTOT];  // A matrix bf16 hi
__device__ __nv_bfloat16 g_Alo[(size_t)N_TGT * KTOT];  // A matrix bf16 lo
__device__ __nv_bfloat16 g_Bhi[(size_t)C * KTOT];      // [o][k] bf16 hi
__device__ __nv_bfloat16 g_Blo[(size_t)C * KTOT];      // [o][k] bf16 lo

// ---------------------------------------------------------------------------
__global__ void zero_small_kernel() {
    int i = blockIdx.x * blockDim.x + threadIdx.x;
    if (i < N_TGT) { g_dcnt[i] = 0; g_cur[i] = 0; }
}

__global__ void hist_kernel(const int* __restrict__ edst) {
    int e = blockIdx.x * blockDim.x + threadIdx.x;
    if (e < N_EDGES) atomicAdd(&g_dcnt[edst[e]], 1);
}

// Single-block exclusive scan of g_dcnt[N_TGT] -> g_doff (4 elems/thread/chunk)
__global__ void scan_kernel() {
    __shared__ int s[1024];
    __shared__ int s_run;
    const int tid = threadIdx.x;
    if (tid == 0) s_run = 0;
    __syncthreads();
    const int CHUNK = 4096;
    const int nch = (N_TGT + CHUNK - 1) / CHUNK;
    for (int c = 0; c < nch; c++) {
        int i0 = c * CHUNK + tid * 4;
        int v0 = (i0 + 0 < N_TGT) ? g_dcnt[i0 + 0] : 0;
        int v1 = (i0 + 1 < N_TGT) ? g_dcnt[i0 + 1] : 0;
        int v2 = (i0 + 2 < N_TGT) ? g_dcnt[i0 + 2] : 0;
        int v3 = (i0 + 3 < N_TGT) ? g_dcnt[i0 + 3] : 0;
        int sum4 = v0 + v1 + v2 + v3;
        s[tid] = sum4;
        __syncthreads();
        // inclusive Hillis-Steele over 1024
        for (int off = 1; off < 1024; off <<= 1) {
            int x = (tid >= off) ? s[tid - off] : 0;
            __syncthreads();
            s[tid] += x;
            __syncthreads();
        }
        int excl = s[tid] - sum4;            // exclusive prefix of sum4
        int total = s[1023];
        int base = s_run + excl;
        if (i0 + 0 < N_TGT) g_doff[i0 + 0] = base;
        if (i0 + 1 < N_TGT) g_doff[i0 + 1] = base + v0;
        if (i0 + 2 < N_TGT) g_doff[i0 + 2] = base + v0 + v1;
        if (i0 + 3 < N_TGT) g_doff[i0 + 3] = base + v0 + v1 + v2;
        __syncthreads();
        if (tid == 0) s_run += total;
        __syncthreads();
    }
    if (tid == 0) g_doff[N_TGT] = s_run;
}

__global__ void fill_kernel(const int* __restrict__ edst) {
    int e = blockIdx.x * blockDim.x + threadIdx.x;
    if (e >= N_EDGES) return;
    int d = edst[e];
    int pos = g_doff[d] + atomicAdd(&g_cur[d], 1);
    g_elist[pos] = e;
}

// ---------------------------------------------------------------------------
// Build B[o][k] split into bf16 hi + lo.
// ---------------------------------------------------------------------------
__global__ void buildB_kernel(const float* __restrict__ rel_w,
                              const float* __restrict__ root_w) {
    int idx = blockIdx.x * blockDim.x + threadIdx.x;
    if (idx >= C * KTOT) return;
    int o = idx / KTOT;
    int k = idx - o * KTOT;
    float w;
    if (k < KREL) {
        w = rel_w[(k >> 7) * (C * C) + o * C + (k & 127)];
    } else {
        int kr = k - KREL;
        w = root_w[(kr >> 7) * (C * C) + o * C + (kr & 127)];
    }
    __nv_bfloat16 hi = __float2bfloat16(w);
    __nv_bfloat16 lo = __float2bfloat16(w - __bfloat162float(hi));
    g_Bhi[idx] = hi;
    g_Blo[idx] = lo;
}

// ---------------------------------------------------------------------------
// Aggregate: one warp per target node. Accumulate per-relation mean of
// gathered x_src rows in fp32 registers, split to bf16 hi/lo, and write the
// full A row (rel slots + type-masked root slots). No atomics, no zero pass.
// ---------------------------------------------------------------------------
__device__ __forceinline__ void write_hilo(size_t idx, float4 v) {
    __nv_bfloat16 hx = __float2bfloat16(v.x);
    __nv_bfloat16 hy = __float2bfloat16(v.y);
    __nv_bfloat16 hz = __float2bfloat16(v.z);
    __nv_bfloat16 hw = __float2bfloat16(v.w);
    __nv_bfloat16 lx = __float2bfloat16(v.x - __bfloat162float(hx));
    __nv_bfloat16 ly = __float2bfloat16(v.y - __bfloat162float(hy));
    __nv_bfloat16 lz = __float2bfloat16(v.z - __bfloat162float(hz));
    __nv_bfloat16 lw = __float2bfloat16(v.w - __bfloat162float(hw));
    *reinterpret_cast<__nv_bfloat162*>(&g_Ahi[idx])     = __nv_bfloat162(hx, hy);
    *reinterpret_cast<__nv_bfloat162*>(&g_Ahi[idx + 2]) = __nv_bfloat162(hz, hw);
    *reinterpret_cast<__nv_bfloat162*>(&g_Alo[idx])     = __nv_bfloat162(lx, ly);
    *reinterpret_cast<__nv_bfloat162*>(&g_Alo[idx + 2]) = __nv_bfloat162(lz, lw);
}

__global__ void aggregate_kernel(const float4* __restrict__ xsrc4,
                                 const float4* __restrict__ xtgt4,
                                 const int* __restrict__ esrc,
                                 const int* __restrict__ etype,
                                 const int* __restrict__ ntype) {
    int gtid = blockIdx.x * blockDim.x + threadIdx.x;
    int d    = gtid >> 5;
    int lane = gtid & 31;
    if (d >= N_TGT) return;

    float4 acc[R];
    int cnt[R];
#pragma unroll
    for (int r = 0; r < R; r++) {
        acc[r] = make_float4(0.f, 0.f, 0.f, 0.f);
        cnt[r] = 0;
    }

    const int beg = g_doff[d];
    const int end = g_doff[d + 1];
    for (int i = beg; i < end; i++) {
        int e  = g_elist[i];
        int s  = esrc[e];
        int re = etype[e];
        float4 v = xsrc4[(size_t)s * 32 + lane];
#pragma unroll
        for (int r = 0; r < R; r++) {
            if (re == r) {
                acc[r].x += v.x; acc[r].y += v.y;
                acc[r].z += v.z; acc[r].w += v.w;
                cnt[r]++;
            }
        }
    }

    const size_t base = (size_t)d * KTOT + lane * 4;
#pragma unroll
    for (int r = 0; r < R; r++) {
        float s = 1.0f / (float)max(cnt[r], 1);
        float4 v = acc[r];
        v.x *= s; v.y *= s; v.z *= s; v.w *= s;
        write_hilo(base + r * C, v);
    }

    // root slots: x_target in the matching type slot, zeros elsewhere
    int t = ntype[d];
    float4 xv = xtgt4[(size_t)d * 32 + lane];
#pragma unroll
    for (int tt = 0; tt < T; tt++) {
        float4 v = (tt == t) ? xv : make_float4(0.f, 0.f, 0.f, 0.f);
        write_hilo(base + KREL + tt * C, v);
    }
}

// ---------------------------------------------------------------------------
// Tensor-core GEMM, register-prefetch pipelined, ldmatrix fragment loads.
// A is now precomputed bf16 hi/lo — the publish phase is pure copies.
// Block 128x128, BK=32, 256 threads / 8 warps (warp tile 32x64).
// ---------------------------------------------------------------------------
__device__ __forceinline__ uint32_t smem_u32(const void* p) {
    return (uint32_t)__cvta_generic_to_shared(p);
}
__device__ __forceinline__ void ldsm_x4(uint32_t& r0, uint32_t& r1,
                                        uint32_t& r2, uint32_t& r3, uint32_t addr) {
    asm volatile("ldmatrix.sync.aligned.m8n8.x4.shared.b16 {%0,%1,%2,%3}, [%4];"
                 : "=r"(r0), "=r"(r1), "=r"(r2), "=r"(r3) : "r"(addr));
}
__device__ __forceinline__ void mma_bf16(float& d0, float& d1, float& d2, float& d3,
                                         uint32_t a0, uint32_t a1, uint32_t a2, uint32_t a3,
                                         uint32_t b0, uint32_t b1) {
    asm volatile(
        "mma.sync.aligned.m16n8k16.row.col.f32.bf16.bf16.f32 "
        "{%0,%1,%2,%3}, {%4,%5,%6,%7}, {%8,%9}, {%0,%1,%2,%3};"
        : "+f"(d0), "+f"(d1), "+f"(d2), "+f"(d3)
        : "r"(a0), "r"(a1), "r"(a2), "r"(a3), "r"(b0), "r"(b1));
}

constexpr int SPAD = 40;  // bf16 elems per smem row (32 data + 8 pad) = 20 words

__global__ __launch_bounds__(256, 1)
void gemm_kernel(const float* __restrict__ root_b,
                 const int* __restrict__ ntype,
                 float* __restrict__ out) {
    __shared__ __nv_bfloat16 As_hi[128][SPAD];
    __shared__ __nv_bfloat16 As_lo[128][SPAD];
    __shared__ __nv_bfloat16 Bs_hi[128][SPAD];
    __shared__ __nv_bfloat16 Bs_lo[128][SPAD];

    const int tid  = threadIdx.x;
    const int lane = tid & 31;
    const int wid  = tid >> 5;
    const int wm   = (wid & 3) * 32;   // warp row offset
    const int wn   = (wid >> 2) * 64;  // warp col offset
    const int row0 = blockIdx.x * 128;
    const int g    = lane >> 2;        // fragment row/col group
    const int t2   = (lane & 3) * 2;   // fragment k pair

    // ldmatrix quadrant addressing
    const int lq  = lane >> 3;
    const int lr8 = lane & 7;
    const int a_ro = ((lq & 1) ? 8 : 0) + lr8;
    const int a_co = (lq & 2) ? 8 : 0;
    const int b_ro = ((lq & 2) ? 8 : 0) + lr8;
    const int b_co = (lq & 1) ? 8 : 0;

    float acc[2][8][4];
#pragma unroll
    for (int i = 0; i < 2; i++)
#pragma unroll
        for (int j = 0; j < 8; j++)
#pragma unroll
            for (int q = 0; q < 4; q++) acc[i][j][q] = 0.f;

    // Tile-loader mapping: thread -> (row = tid>>1, 16 consecutive k)
    const int lrow = tid >> 1;
    const int lkof = (tid & 1) * 16;
    const int dmy  = row0 + lrow;

    // ---- prefetch registers (A hi/lo + B hi/lo, 16 bf16 each) ----
    uint4 pah0, pah1, pal0, pal1, pbh0, pbh1, pbl0, pbl1;

#define PREFETCH(KB_)                                                          \
    do {                                                                       \
        const int kb_ = (KB_);                                                 \
        if (dmy < N_TGT) {                                                     \
            const size_t aof_ = (size_t)dmy * KTOT + kb_ + lkof;               \
            pah0 = *reinterpret_cast<const uint4*>(&g_Ahi[aof_]);              \
            pah1 = *reinterpret_cast<const uint4*>(&g_Ahi[aof_ + 8]);          \
            pal0 = *reinterpret_cast<const uint4*>(&g_Alo[aof_]);              \
            pal1 = *reinterpret_cast<const uint4*>(&g_Alo[aof_ + 8]);          \
        } else {                                                               \
            pah0 = pah1 = pal0 = pal1 = make_uint4(0, 0, 0, 0);                \
        }                                                                      \
        const size_t gof_ = (size_t)lrow * KTOT + kb_ + lkof;                  \
        pbh0 = *reinterpret_cast<const uint4*>(&g_Bhi[gof_]);                  \
        pbh1 = *reinterpret_cast<const uint4*>(&g_Bhi[gof_ + 8]);              \
        pbl0 = *reinterpret_cast<const uint4*>(&g_Blo[gof_]);                  \
        pbl1 = *reinterpret_cast<const uint4*>(&g_Blo[gof_ + 8]);              \
    } while (0)

    PREFETCH(0);

    for (int kb = 0; kb < KTOT; kb += 32) {
        // ---- publish prefetched tiles (pure copies) ----
        *reinterpret_cast<uint4*>(&As_hi[lrow][lkof])     = pah0;
        *reinterpret_cast<uint4*>(&As_hi[lrow][lkof + 8]) = pah1;
        *reinterpret_cast<uint4*>(&As_lo[lrow][lkof])     = pal0;
        *reinterpret_cast<uint4*>(&As_lo[lrow][lkof + 8]) = pal1;
        *reinterpret_cast<uint4*>(&Bs_hi[lrow][lkof])     = pbh0;
        *reinterpret_cast<uint4*>(&Bs_hi[lrow][lkof + 8]) = pbh1;
        *reinterpret_cast<uint4*>(&Bs_lo[lrow][lkof])     = pbl0;
        *reinterpret_cast<uint4*>(&Bs_lo[lrow][lkof + 8]) = pbl1;
        __syncthreads();

        // ---- prefetch next iteration ----
        if (kb + 32 < KTOT) PREFETCH(kb + 32);

        // ---- compute: 2 k16 steps, 3 split passes, ldmatrix loads ----
#pragma unroll
        for (int ks = 0; ks < 2; ks++) {
            const int k0 = ks * 16;
            uint32_t ah[2][4], al[2][4];
#pragma unroll
            for (int mt = 0; mt < 2; mt++) {
                int r = wm + mt * 16 + a_ro;
                ldsm_x4(ah[mt][0], ah[mt][1], ah[mt][2], ah[mt][3],
                        smem_u32(&As_hi[r][k0 + a_co]));
                ldsm_x4(al[mt][0], al[mt][1], al[mt][2], al[mt][3],
                        smem_u32(&As_lo[r][k0 + a_co]));
            }
            uint32_t bh[8][2], bl[8][2];
#pragma unroll
            for (int p = 0; p < 4; p++) {
                int n = wn + p * 16 + b_ro;
                uint32_t r0, r1, r2, r3;
                ldsm_x4(r0, r1, r2, r3, smem_u32(&Bs_hi[n][k0 + b_co]));
                bh[2 * p][0] = r0; bh[2 * p][1] = r1;
                bh[2 * p + 1][0] = r2; bh[2 * p + 1][1] = r3;
                ldsm_x4(r0, r1, r2, r3, smem_u32(&Bs_lo[n][k0 + b_co]));
                bl[2 * p][0] = r0; bl[2 * p][1] = r1;
                bl[2 * p + 1][0] = r2; bl[2 * p + 1][1] = r3;
            }
#pragma unroll
            for (int mt = 0; mt < 2; mt++)
#pragma unroll
                for (int nt = 0; nt < 8; nt++) {
                    mma_bf16(acc[mt][nt][0], acc[mt][nt][1], acc[mt][nt][2], acc[mt][nt][3],
                             ah[mt][0], ah[mt][1], ah[mt][2], ah[mt][3],
                             bh[nt][0], bh[nt][1]);
                    mma_bf16(acc[mt][nt][0], acc[mt][nt][1], acc[mt][nt][2], acc[mt][nt][3],
                             ah[mt][0], ah[mt][1], ah[mt][2], ah[mt][3],
                             bl[nt][0], bl[nt][1]);
                    mma_bf16(acc[mt][nt][0], acc[mt][nt][1], acc[mt][nt][2], acc[mt][nt][3],
                             al[mt][0], al[mt][1], al[mt][2], al[mt][3],
                             bh[nt][0], bh[nt][1]);
                }
        }
        __syncthreads();
    }
#undef PREFETCH

    // ---- epilogue: add root bias, store float2 per fragment half ----
#pragma unroll
    for (int mt = 0; mt < 2; mt++) {
#pragma unroll
        for (int half = 0; half < 2; half++) {
            int d = row0 + wm + mt * 16 + g + half * 8;
            if (d >= N_TGT) continue;
            int t = ntype[d];
            const float* bias = &root_b[t * C];
            float* orow = &out[(size_t)d * C];
#pragma unroll
            for (int nt = 0; nt < 8; nt++) {
                int col = wn + nt * 8 + t2;
                float2 w;
                w.x = acc[mt][nt][2 * half + 0] + bias[col + 0];
                w.y = acc[mt][nt][2 * half + 1] + bias[col + 1];
                *reinterpret_cast<float2*>(&orow[col]) = w;
            }
        }
    }
}

// ---------------------------------------------------------------------------
extern "C" void kernel_launch(void* const* d_in, const int* in_sizes, int n_in,
                              void* d_out, int out_size) {
    const float* x_src     = (const float*)d_in[0];
    const float* x_target  = (const float*)d_in[1];
    const float* rel_w     = (const float*)d_in[2];
    const float* root_w    = (const float*)d_in[3];
    const float* root_b    = (const float*)d_in[4];
    const int*   edge_src  = (const int*)d_in[5];
    const int*   edge_dst  = (const int*)d_in[6];
    const int*   edge_type = (const int*)d_in[7];
    const int*   ntype     = (const int*)d_in[8];
    float*       out       = (float*)d_out;

    (void)in_sizes; (void)n_in; (void)out_size;

    zero_small_kernel<<<(N_TGT + 255) / 256, 256>>>();
    hist_kernel<<<(N_EDGES + 255) / 256, 256>>>(edge_dst);
    scan_kernel<<<1, 1024>>>();
    fill_kernel<<<(N_EDGES + 255) / 256, 256>>>(edge_dst);
    buildB_kernel<<<(C * KTOT + 255) / 256, 256>>>(rel_w, root_w);
    aggregate_kernel<<<(N_TGT * 32 + 255) / 256, 256>>>(
        (const float4*)x_src, (const float4*)x_target,
        edge_src, edge_type, ntype);
    gemm_kernel<<<(N_TGT + 127) / 128, 256>>>(root_b, ntype, out);
}

// round 11
// speedup vs baseline: 1.2372x; 1.2372x over previous
#include <cuda_runtime.h>
#include <cuda_bf16.h>
#include <cstdint>

// Problem constants (fixed by the dataset)
constexpr int N_SRC   = 100000;
constexpr int N_TGT   = 50000;
constexpr int N_EDGES = 600000;
constexpr int C       = 128;   // in/out channels
constexpr int R       = 7;     // edge types
constexpr int T       = 4;     // node types
constexpr int KREL    = R * C;        // 896
constexpr int KTOT    = KREL + T * C; // 1408
constexpr int NBLK    = (N_TGT + 255) / 256;   // 196 scan blocks

// Scratch (static __device__ arrays: allocation-free per harness rules)
__device__ int g_dcnt[N_TGT];          // per-dst edge count (histogram)
__device__ int g_doff[N_TGT + 1];      // CSR offsets
__device__ int g_cur[N_TGT];           // fill cursors (init = doff)
__device__ int g_bsum[NBLK];           // per-block sums
__device__ int g_bpre[NBLK];           // exclusive prefix of block sums
__device__ int g_elist[N_EDGES];       // packed (src | etype<<20), CSR order
__device__ __nv_bfloat16 g_Ahi[(size_t)N_TGT * KREL];  // A rel-slots bf16 hi
__device__ __nv_bfloat16 g_Alo[(size_t)N_TGT * KREL];  // A rel-slots bf16 lo
__device__ __nv_bfloat16 g_Bhi[(size_t)C * KTOT];      // [o][k] bf16 hi
__device__ __nv_bfloat16 g_Blo[(size_t)C * KTOT];      // [o][k] bf16 lo

// ---------------------------------------------------------------------------
__global__ void zero_small_kernel() {
    int i = blockIdx.x * blockDim.x + threadIdx.x;
    if (i < N_TGT) g_dcnt[i] = 0;
}

__global__ void hist_kernel(const int* __restrict__ edst) {
    int e = blockIdx.x * blockDim.x + threadIdx.x;
    if (e < N_EDGES) atomicAdd(&g_dcnt[edst[e]], 1);
}

// Per-block sums of g_dcnt (grid = NBLK)
__global__ void block_sum_kernel() {
    __shared__ int s[256];
    int i = blockIdx.x * 256 + threadIdx.x;
    s[threadIdx.x] = (i < N_TGT) ? g_dcnt[i] : 0;
    __syncthreads();
    for (int o = 128; o > 0; o >>= 1) {
        if (threadIdx.x < o) s[threadIdx.x] += s[threadIdx.x + o];
        __syncthreads();
    }
    if (threadIdx.x == 0) g_bsum[blockIdx.x] = s[0];
}

// Scan the NBLK block sums (1 block of 256)
__global__ void scan_bsum_kernel() {
    __shared__ int s[256];
    int v = (threadIdx.x < NBLK) ? g_bsum[threadIdx.x] : 0;
    s[threadIdx.x] = v;
    __syncthreads();
    for (int o = 1; o < 256; o <<= 1) {
        int x = (threadIdx.x >= o) ? s[threadIdx.x - o] : 0;
        __syncthreads();
        s[threadIdx.x] += x;
        __syncthreads();
    }
    if (threadIdx.x < NBLK) g_bpre[threadIdx.x] = s[threadIdx.x] - v;
    if (threadIdx.x == 255) g_doff[N_TGT] = s[255];
}

// Final offsets: intra-block exclusive scan + block prefix; also init cursors.
__global__ void offsets_kernel() {
    __shared__ int s[256];
    int i = blockIdx.x * 256 + threadIdx.x;
    int v = (i < N_TGT) ? g_dcnt[i] : 0;
    s[threadIdx.x] = v;
    __syncthreads();
    for (int o = 1; o < 256; o <<= 1) {
        int x = (threadIdx.x >= o) ? s[threadIdx.x - o] : 0;
        __syncthreads();
        s[threadIdx.x] += x;
        __syncthreads();
    }
    int excl = s[threadIdx.x] - v + g_bpre[blockIdx.x];
    if (i < N_TGT) {
        g_doff[i] = excl;
        g_cur[i]  = excl;
    }
}

// Fill CSR with packed (src | etype<<20). N_SRC < 2^20 so the pack is exact.
__global__ void fill_kernel(const int* __restrict__ esrc,
                            const int* __restrict__ edst,
                            const int* __restrict__ etype) {
    int e = blockIdx.x * blockDim.x + threadIdx.x;
    if (e >= N_EDGES) return;
    int d = edst[e];
    int pos = atomicAdd(&g_cur[d], 1);
    g_elist[pos] = esrc[e] | (etype[e] << 20);
}

// ---------------------------------------------------------------------------
// Build B[o][k] split into bf16 hi + lo.
// ---------------------------------------------------------------------------
__global__ void buildB_kernel(const float* __restrict__ rel_w,
                              const float* __restrict__ root_w) {
    int idx = blockIdx.x * blockDim.x + threadIdx.x;
    if (idx >= C * KTOT) return;
    int o = idx / KTOT;
    int k = idx - o * KTOT;
    float w;
    if (k < KREL) {
        w = rel_w[(k >> 7) * (C * C) + o * C + (k & 127)];
    } else {
        int kr = k - KREL;
        w = root_w[(kr >> 7) * (C * C) + o * C + (kr & 127)];
    }
    __nv_bfloat16 hi = __float2bfloat16(w);
    __nv_bfloat16 lo = __float2bfloat16(w - __bfloat162float(hi));
    g_Bhi[idx] = hi;
    g_Blo[idx] = lo;
}

// ---------------------------------------------------------------------------
// Aggregate: one warp per target node. Packed CSR entries, unroll-2 for MLP.
// Writes ONLY the 7 relation slots (bf16 hi/lo), pre-normalized by 1/cnt.
// ---------------------------------------------------------------------------
__device__ __forceinline__ void hilo2(float x, float y, uint32_t& h, uint32_t& l) {
    __nv_bfloat16 hx = __float2bfloat16(x);
    __nv_bfloat16 hy = __float2bfloat16(y);
    __nv_bfloat16 lx = __float2bfloat16(x - __bfloat162float(hx));
    __nv_bfloat16 ly = __float2bfloat16(y - __bfloat162float(hy));
    __nv_bfloat162 hh(hx, hy), ll(lx, ly);
    h = *reinterpret_cast<uint32_t*>(&hh);
    l = *reinterpret_cast<uint32_t*>(&ll);
}

__device__ __forceinline__ void write_hilo(size_t idx, float4 v) {
    uint32_t h0, h1, l0, l1;
    hilo2(v.x, v.y, h0, l0);
    hilo2(v.z, v.w, h1, l1);
    *reinterpret_cast<uint32_t*>(&g_Ahi[idx])     = h0;
    *reinterpret_cast<uint32_t*>(&g_Ahi[idx + 2]) = h1;
    *reinterpret_cast<uint32_t*>(&g_Alo[idx])     = l0;
    *reinterpret_cast<uint32_t*>(&g_Alo[idx + 2]) = l1;
}

__global__ void aggregate_kernel(const float4* __restrict__ xsrc4) {
    int gtid = blockIdx.x * blockDim.x + threadIdx.x;
    int d    = gtid >> 5;
    int lane = gtid & 31;
    if (d >= N_TGT) return;

    float4 acc[R];
    int cnt[R];
#pragma unroll
    for (int r = 0; r < R; r++) {
        acc[r] = make_float4(0.f, 0.f, 0.f, 0.f);
        cnt[r] = 0;
    }

    const int beg = g_doff[d];
    const int end = g_doff[d + 1];
    int i = beg;
    for (; i + 2 <= end; i += 2) {
        int p0 = g_elist[i];
        int p1 = g_elist[i + 1];
        int s0 = p0 & 0xFFFFF, r0 = p0 >> 20;
        int s1 = p1 & 0xFFFFF, r1 = p1 >> 20;
        float4 v0 = xsrc4[(size_t)s0 * 32 + lane];
        float4 v1 = xsrc4[(size_t)s1 * 32 + lane];
#pragma unroll
        for (int r = 0; r < R; r++) {
            if (r0 == r) {
                acc[r].x += v0.x; acc[r].y += v0.y;
                acc[r].z += v0.z; acc[r].w += v0.w;
                cnt[r]++;
            }
            if (r1 == r) {
                acc[r].x += v1.x; acc[r].y += v1.y;
                acc[r].z += v1.z; acc[r].w += v1.w;
                cnt[r]++;
            }
        }
    }
    if (i < end) {
        int p0 = g_elist[i];
        int s0 = p0 & 0xFFFFF, r0 = p0 >> 20;
        float4 v0 = xsrc4[(size_t)s0 * 32 + lane];
#pragma unroll
        for (int r = 0; r < R; r++) {
            if (r0 == r) {
                acc[r].x += v0.x; acc[r].y += v0.y;
                acc[r].z += v0.z; acc[r].w += v0.w;
                cnt[r]++;
            }
        }
    }

    const size_t base = (size_t)d * KREL + lane * 4;
#pragma unroll
    for (int r = 0; r < R; r++) {
        float s = 1.0f / (float)max(cnt[r], 1);
        float4 v = acc[r];
        v.x *= s; v.y *= s; v.z *= s; v.w *= s;
        write_hilo(base + r * C, v);
    }
}

// ---------------------------------------------------------------------------
// Tensor-core GEMM, register-prefetch pipelined, ldmatrix fragment loads.
// Rel slots (kb < 896): pure bf16 copies from g_Ahi/g_Alo.
// Root slots (kb >= 896): x_target fp32 loaded + converted in PREFETCH.
// Block 128x128, BK=32, 256 threads / 8 warps (warp tile 32x64).
// ---------------------------------------------------------------------------
__device__ __forceinline__ uint32_t smem_u32(const void* p) {
    return (uint32_t)__cvta_generic_to_shared(p);
}
__device__ __forceinline__ void ldsm_x4(uint32_t& r0, uint32_t& r1,
                                        uint32_t& r2, uint32_t& r3, uint32_t addr) {
    asm volatile("ldmatrix.sync.aligned.m8n8.x4.shared.b16 {%0,%1,%2,%3}, [%4];"
                 : "=r"(r0), "=r"(r1), "=r"(r2), "=r"(r3) : "r"(addr));
}
__device__ __forceinline__ void mma_bf16(float& d0, float& d1, float& d2, float& d3,
                                         uint32_t a0, uint32_t a1, uint32_t a2, uint32_t a3,
                                         uint32_t b0, uint32_t b1) {
    asm volatile(
        "mma.sync.aligned.m16n8k16.row.col.f32.bf16.bf16.f32 "
        "{%0,%1,%2,%3}, {%4,%5,%6,%7}, {%8,%9}, {%0,%1,%2,%3};"
        : "+f"(d0), "+f"(d1), "+f"(d2), "+f"(d3)
        : "r"(a0), "r"(a1), "r"(a2), "r"(a3), "r"(b0), "r"(b1));
}

constexpr int SPAD = 40;  // bf16 elems per smem row (32 data + 8 pad) = 20 words

__global__ __launch_bounds__(256, 1)
void gemm_kernel(const float* __restrict__ x_target,
                 const float* __restrict__ root_b,
                 const int* __restrict__ ntype,
                 float* __restrict__ out) {
    __shared__ __nv_bfloat16 As_hi[128][SPAD];
    __shared__ __nv_bfloat16 As_lo[128][SPAD];
    __shared__ __nv_bfloat16 Bs_hi[128][SPAD];
    __shared__ __nv_bfloat16 Bs_lo[128][SPAD];

    const int tid  = threadIdx.x;
    const int lane = tid & 31;
    const int wid  = tid >> 5;
    const int wm   = (wid & 3) * 32;   // warp row offset
    const int wn   = (wid >> 2) * 64;  // warp col offset
    const int row0 = blockIdx.x * 128;
    const int g    = lane >> 2;        // fragment row/col group
    const int t2   = (lane & 3) * 2;   // fragment k pair

    // ldmatrix quadrant addressing
    const int lq  = lane >> 3;
    const int lr8 = lane & 7;
    const int a_ro = ((lq & 1) ? 8 : 0) + lr8;
    const int a_co = (lq & 2) ? 8 : 0;
    const int b_ro = ((lq & 2) ? 8 : 0) + lr8;
    const int b_co = (lq & 1) ? 8 : 0;

    float acc[2][8][4];
#pragma unroll
    for (int i = 0; i < 2; i++)
#pragma unroll
        for (int j = 0; j < 8; j++)
#pragma unroll
            for (int q = 0; q < 4; q++) acc[i][j][q] = 0.f;

    // Tile-loader mapping: thread -> (row = tid>>1, 16 consecutive k)
    const int lrow = tid >> 1;
    const int lkof = (tid & 1) * 16;
    const int dmy  = row0 + lrow;
    const int myt  = (dmy < N_TGT) ? ntype[dmy] : -1;

    // ---- prefetch registers ----
    uint4 pah0, pah1, pal0, pal1, pbh0, pbh1, pbl0, pbl1;

#define PREFETCH(KB_)                                                          \
    do {                                                                       \
        const int kb_ = (KB_);                                                 \
        if (kb_ < KREL) {                                                      \
            if (dmy < N_TGT) {                                                 \
                const size_t aof_ = (size_t)dmy * KREL + kb_ + lkof;           \
                pah0 = *reinterpret_cast<const uint4*>(&g_Ahi[aof_]);          \
                pah1 = *reinterpret_cast<const uint4*>(&g_Ahi[aof_ + 8]);      \
                pal0 = *reinterpret_cast<const uint4*>(&g_Alo[aof_]);          \
                pal1 = *reinterpret_cast<const uint4*>(&g_Alo[aof_ + 8]);      \
            } else {                                                           \
                pah0 = pah1 = pal0 = pal1 = make_uint4(0, 0, 0, 0);            \
            }                                                                  \
        } else {                                                               \
            const int kr_ = kb_ - KREL;                                        \
            float4 pv[4];                                                      \
            if (dmy < N_TGT && myt == (kr_ >> 7)) {                            \
                const float* xp_ = &x_target[(size_t)dmy * C + (kr_ & 127) + lkof]; \
                pv[0] = *reinterpret_cast<const float4*>(xp_);                 \
                pv[1] = *reinterpret_cast<const float4*>(xp_ + 4);             \
                pv[2] = *reinterpret_cast<const float4*>(xp_ + 8);             \
                pv[3] = *reinterpret_cast<const float4*>(xp_ + 12);            \
            } else {                                                           \
                pv[0] = pv[1] = pv[2] = pv[3] = make_float4(0.f, 0.f, 0.f, 0.f); \
            }                                                                  \
            uint32_t h_[8], l_[8];                                             \
            hilo2(pv[0].x, pv[0].y, h_[0], l_[0]);                             \
            hilo2(pv[0].z, pv[0].w, h_[1], l_[1]);                             \
            hilo2(pv[1].x, pv[1].y, h_[2], l_[2]);                             \
            hilo2(pv[1].z, pv[1].w, h_[3], l_[3]);                             \
            hilo2(pv[2].x, pv[2].y, h_[4], l_[4]);                             \
            hilo2(pv[2].z, pv[2].w, h_[5], l_[5]);                             \
            hilo2(pv[3].x, pv[3].y, h_[6], l_[6]);                             \
            hilo2(pv[3].z, pv[3].w, h_[7], l_[7]);                             \
            pah0 = make_uint4(h_[0], h_[1], h_[2], h_[3]);                     \
            pah1 = make_uint4(h_[4], h_[5], h_[6], h_[7]);                     \
            pal0 = make_uint4(l_[0], l_[1], l_[2], l_[3]);                     \
            pal1 = make_uint4(l_[4], l_[5], l_[6], l_[7]);                     \
        }                                                                      \
        const size_t gof_ = (size_t)lrow * KTOT + kb_ + lkof;                  \
        pbh0 = *reinterpret_cast<const uint4*>(&g_Bhi[gof_]);                  \
        pbh1 = *reinterpret_cast<const uint4*>(&g_Bhi[gof_ + 8]);              \
        pbl0 = *reinterpret_cast<const uint4*>(&g_Blo[gof_]);                  \
        pbl1 = *reinterpret_cast<const uint4*>(&g_Blo[gof_ + 8]);              \
    } while (0)

    PREFETCH(0);

    for (int kb = 0; kb < KTOT; kb += 32) {
        // ---- publish prefetched tiles (pure copies) ----
        *reinterpret_cast<uint4*>(&As_hi[lrow][lkof])     = pah0;
        *reinterpret_cast<uint4*>(&As_hi[lrow][lkof + 8]) = pah1;
        *reinterpret_cast<uint4*>(&As_lo[lrow][lkof])     = pal0;
        *reinterpret_cast<uint4*>(&As_lo[lrow][lkof + 8]) = pal1;
        *reinterpret_cast<uint4*>(&Bs_hi[lrow][lkof])     = pbh0;
        *reinterpret_cast<uint4*>(&Bs_hi[lrow][lkof + 8]) = pbh1;
        *reinterpret_cast<uint4*>(&Bs_lo[lrow][lkof])     = pbl0;
        *reinterpret_cast<uint4*>(&Bs_lo[lrow][lkof + 8]) = pbl1;
        __syncthreads();

        // ---- prefetch next iteration ----
        if (kb + 32 < KTOT) PREFETCH(kb + 32);

        // ---- compute: 2 k16 steps, 3 split passes, ldmatrix loads ----
#pragma unroll
        for (int ks = 0; ks < 2; ks++) {
            const int k0 = ks * 16;
            uint32_t ah[2][4], al[2][4];
#pragma unroll
            for (int mt = 0; mt < 2; mt++) {
                int r = wm + mt * 16 + a_ro;
                ldsm_x4(ah[mt][0], ah[mt][1], ah[mt][2], ah[mt][3],
                        smem_u32(&As_hi[r][k0 + a_co]));
                ldsm_x4(al[mt][0], al[mt][1], al[mt][2], al[mt][3],
                        smem_u32(&As_lo[r][k0 + a_co]));
            }
            uint32_t bh[8][2], bl[8][2];
#pragma unroll
            for (int p = 0; p < 4; p++) {
                int n = wn + p * 16 + b_ro;
                uint32_t r0, r1, r2, r3;
                ldsm_x4(r0, r1, r2, r3, smem_u32(&Bs_hi[n][k0 + b_co]));
                bh[2 * p][0] = r0; bh[2 * p][1] = r1;
                bh[2 * p + 1][0] = r2; bh[2 * p + 1][1] = r3;
                ldsm_x4(r0, r1, r2, r3, smem_u32(&Bs_lo[n][k0 + b_co]));
                bl[2 * p][0] = r0; bl[2 * p][1] = r1;
                bl[2 * p + 1][0] = r2; bl[2 * p + 1][1] = r3;
            }
#pragma unroll
            for (int mt = 0; mt < 2; mt++)
#pragma unroll
                for (int nt = 0; nt < 8; nt++) {
                    mma_bf16(acc[mt][nt][0], acc[mt][nt][1], acc[mt][nt][2], acc[mt][nt][3],
                             ah[mt][0], ah[mt][1], ah[mt][2], ah[mt][3],
                             bh[nt][0], bh[nt][1]);
                    mma_bf16(acc[mt][nt][0], acc[mt][nt][1], acc[mt][nt][2], acc[mt][nt][3],
                             ah[mt][0], ah[mt][1], ah[mt][2], ah[mt][3],
                             bl[nt][0], bl[nt][1]);
                    mma_bf16(acc[mt][nt][0], acc[mt][nt][1], acc[mt][nt][2], acc[mt][nt][3],
                             al[mt][0], al[mt][1], al[mt][2], al[mt][3],
                             bh[nt][0], bh[nt][1]);
                }
        }
        __syncthreads();
    }
#undef PREFETCH

    // ---- epilogue: add root bias, store float2 per fragment half ----
#pragma unroll
    for (int mt = 0; mt < 2; mt++) {
#pragma unroll
        for (int half = 0; half < 2; half++) {
            int d = row0 + wm + mt * 16 + g + half * 8;
            if (d >= N_TGT) continue;
            int t = ntype[d];
            const float* bias = &root_b[t * C];
            float* orow = &out[(size_t)d * C];
#pragma unroll
            for (int nt = 0; nt < 8; nt++) {
                int col = wn + nt * 8 + t2;
                float2 w;
                w.x = acc[mt][nt][2 * half + 0] + bias[col + 0];
                w.y = acc[mt][nt][2 * half + 1] + bias[col + 1];
                *reinterpret_cast<float2*>(&orow[col]) = w;
            }
        }
    }
}

// ---------------------------------------------------------------------------
extern "C" void kernel_launch(void* const* d_in, const int* in_sizes, int n_in,
                              void* d_out, int out_size) {
    const float* x_src     = (const float*)d_in[0];
    const float* x_target  = (const float*)d_in[1];
    const float* rel_w     = (const float*)d_in[2];
    const float* root_w    = (const float*)d_in[3];
    const float* root_b    = (const float*)d_in[4];
    const int*   edge_src  = (const int*)d_in[5];
    const int*   edge_dst  = (const int*)d_in[6];
    const int*   edge_type = (const int*)d_in[7];
    const int*   ntype     = (const int*)d_in[8];
    float*       out       = (float*)d_out;

    (void)in_sizes; (void)n_in; (void)out_size;

    zero_small_kernel<<<(N_TGT + 255) / 256, 256>>>();
    hist_kernel<<<(N_EDGES + 255) / 256, 256>>>(edge_dst);
    block_sum_kernel<<<NBLK, 256>>>();
    scan_bsum_kernel<<<1, 256>>>();
    offsets_kernel<<<NBLK, 256>>>();
    fill_kernel<<<(N_EDGES + 255) / 256, 256>>>(edge_src, edge_dst, edge_type);
    buildB_kernel<<<(C * KTOT + 255) / 256, 256>>>(rel_w, root_w);
    aggregate_kernel<<<(N_TGT * 32 + 255) / 256, 256>>>((const float4*)x_src);
    gemm_kernel<<<(N_TGT + 127) / 128, 256>>>(x_target, root_b, ntype, out);
}